// round 4
// baseline (speedup 1.0000x reference)
#include <cuda_runtime.h>
#include <math.h>

// ---------------- scratch (device globals; no allocation) ----------------
__device__ float g_t2[64*4*64*64];      // conv2 out
__device__ float g_di[64*4*64*64];      // post-VQ 1x1 out
__device__ float g_partA[1024*32];
__device__ float g_partC[1024*8];
__device__ float g_partE[1024];
__device__ float g_partF[2048*16];
__device__ float g_partH[4096];
__device__ float g_bn1[32];  // scale[16], shift[16]
__device__ float g_bn2[8];   // scale[4], shift[4]
__device__ float g_bn3[32];

__device__ __forceinline__ float warp_sum(float v){
#pragma unroll
  for (int o = 16; o > 0; o >>= 1) v += __shfl_down_sync(0xffffffffu, v, o);
  return v;
}

// ---------------- kernel 1: conv1 (1->16, k4 s2 p1) BN1 partials ONLY ----------------
__global__ void k_conv1s(const float* __restrict__ x, const float* __restrict__ w1,
                         const float* __restrict__ b1){
  __shared__ float s_in[66*68];
  __shared__ float s_w[256];
  __shared__ float s_b[16];
  __shared__ float s_red[8*32];
  const int bz = blockIdx.z;
  const int ox0 = blockIdx.x*32, oy0 = blockIdx.y*32;
  const int tid = threadIdx.y*32 + threadIdx.x;
  s_w[tid] = w1[tid];
  if (tid < 16) s_b[tid] = b1[tid];
  const float* xb = x + (size_t)bz*65536;
  for (int j = tid; j < 66*66; j += 256){
    int r = j/66, c = j - r*66;
    int gr = oy0*2 - 1 + r, gc = ox0*2 - 1 + c;
    float v = 0.f;
    if ((unsigned)gr < 256u && (unsigned)gc < 256u) v = xb[gr*256 + gc];
    s_in[r*68 + c] = v;
  }
  __syncthreads();
  float st[32];
#pragma unroll
  for (int v = 0; v < 32; v++) st[v] = 0.f;
#pragma unroll
  for (int k = 0; k < 4; k++){
    int ty = threadIdx.y + k*8;
    int tx = threadIdx.x;
    float p[16];
#pragma unroll
    for (int r = 0; r < 4; r++)
#pragma unroll
      for (int c = 0; c < 4; c++)
        p[r*4+c] = s_in[(2*ty+r)*68 + 2*tx + c];
#pragma unroll
    for (int oc = 0; oc < 16; oc++){
      float acc = s_b[oc];
#pragma unroll
      for (int j = 0; j < 16; j++) acc = fmaf(p[j], s_w[oc*16 + j], acc);
      st[oc] += acc;
      st[16+oc] = fmaf(acc, acc, st[16+oc]);
    }
  }
  int lane = tid & 31, warp = tid >> 5;
#pragma unroll
  for (int v = 0; v < 32; v++){
    float r = warp_sum(st[v]);
    if (lane == 0) s_red[warp*32 + v] = r;
  }
  __syncthreads();
  if (tid < 32){
    float t = 0.f;
#pragma unroll
    for (int w = 0; w < 8; w++) t += s_red[w*32 + tid];
    int blk = (blockIdx.z*4 + blockIdx.y)*4 + blockIdx.x;
    g_partA[blk*32 + tid] = t;
  }
}

// ---------------- BN1 finalize: partA [1024][32] ----------------
__global__ void k_bnfinA(const float* __restrict__ g, const float* __restrict__ be){
  const int c = blockIdx.x;
  const int tid = threadIdx.x;
  double s = 0.0, q = 0.0;
  for (int i = tid; i < 1024; i += 256){
    s += (double)g_partA[i*32 + c];
    q += (double)g_partA[i*32 + 16 + c];
  }
#pragma unroll
  for (int o = 16; o > 0; o >>= 1){
    s += __shfl_down_sync(0xffffffffu, s, o);
    q += __shfl_down_sync(0xffffffffu, q, o);
  }
  __shared__ double ss[8], qq[8];
  int lane = tid & 31, warp = tid >> 5;
  if (lane == 0){ ss[warp] = s; qq[warp] = q; }
  __syncthreads();
  if (tid == 0){
    double S = 0.0, Q = 0.0;
#pragma unroll
    for (int w = 0; w < 8; w++){ S += ss[w]; Q += qq[w]; }
    const double invN = 1.0/1048576.0;
    double mean = S*invN;
    double var  = Q*invN - mean*mean;
    float scale = (float)((double)g[c] / sqrt(var + 1e-5));
    g_bn1[c] = scale;
    g_bn1[16 + c] = be[c] - (float)mean * scale;
  }
}

// ---------------- BN3 finalize: partF [2048][16] split oc-group ----------------
__global__ void k_bnfinF(const float* __restrict__ g, const float* __restrict__ be){
  const int c = blockIdx.x;
  const int gi = c >> 3, j = c & 7;
  const int tid = threadIdx.x;
  double s = 0.0, q = 0.0;
  for (int i = tid; i < 1024; i += 256){
    int z = 2*(i >> 4) + gi;
    int blk = z*16 + (i & 15);
    s += (double)g_partF[blk*16 + j];
    q += (double)g_partF[blk*16 + 8 + j];
  }
#pragma unroll
  for (int o = 16; o > 0; o >>= 1){
    s += __shfl_down_sync(0xffffffffu, s, o);
    q += __shfl_down_sync(0xffffffffu, q, o);
  }
  __shared__ double ss[8], qq[8];
  int lane = tid & 31, warp = tid >> 5;
  if (lane == 0){ ss[warp] = s; qq[warp] = q; }
  __syncthreads();
  if (tid == 0){
    double S = 0.0, Q = 0.0;
#pragma unroll
    for (int w = 0; w < 8; w++){ S += ss[w]; Q += qq[w]; }
    const double invN = 1.0/1048576.0;
    double mean = S*invN;
    double var  = Q*invN - mean*mean;
    float scale = (float)((double)g[c] / sqrt(var + 1e-5));
    g_bn3[c] = scale;
    g_bn3[16 + c] = be[c] - (float)mean * scale;
  }
}

// ---------------- BN2 finalize: partC [1024][8] ----------------
__global__ void k_bnfin4(const float* __restrict__ g, const float* __restrict__ be){
  const int c = blockIdx.x;
  const int tid = threadIdx.x;
  double s = 0.0, q = 0.0;
  for (int i = tid; i < 1024; i += 256){
    s += (double)g_partC[i*8 + c];
    q += (double)g_partC[i*8 + 4 + c];
  }
#pragma unroll
  for (int o = 16; o > 0; o >>= 1){
    s += __shfl_down_sync(0xffffffffu, s, o);
    q += __shfl_down_sync(0xffffffffu, q, o);
  }
  __shared__ double ss[8], qq[8];
  int lane = tid & 31, warp = tid >> 5;
  if (lane == 0){ ss[warp] = s; qq[warp] = q; }
  __syncthreads();
  if (tid == 0){
    double S = 0.0, Q = 0.0;
#pragma unroll
    for (int w = 0; w < 8; w++){ S += ss[w]; Q += qq[w]; }
    const double invN = 1.0/262144.0;
    double mean = S*invN;
    double var  = Q*invN - mean*mean;
    float scale = (float)((double)g[c] / sqrt(var + 1e-5));
    g_bn2[c] = scale;
    g_bn2[4 + c] = be[c] - (float)mean * scale;
  }
}

// ---------------- kernel 3: fused conv1-recompute + BN1 + ReLU + conv2 + BN2 partials ----------------
// grid (4,4,64), block (16,16). 16x16 t2 tile <- 34x34 t1 tile <- 70x70 x tile.
__global__ void k_conv2f(const float* __restrict__ x,
                         const float* __restrict__ w1, const float* __restrict__ b1,
                         const float* __restrict__ w2, const float* __restrict__ b2){
  __shared__ float s_x[70*71];
  __shared__ float s_t1[4*34*35];
  __shared__ float s_w1[256];
  __shared__ float s_b1[16];
  __shared__ float s_w2[1024];
  __shared__ float s_b2[4];
  __shared__ float s_bn[32];
  __shared__ float s_red[8*8];
  const int bz = blockIdx.z;
  const int ox0 = blockIdx.x*16, oy0 = blockIdx.y*16;   // t2 coords (64x64)
  const int tid = threadIdx.y*16 + threadIdx.x;
  s_w1[tid] = w1[tid];
  for (int j = tid; j < 1024; j += 256) s_w2[j] = w2[j];
  if (tid < 16) s_b1[tid] = b1[tid];
  if (tid < 4)  s_b2[tid] = b2[tid];
  if (tid < 32) s_bn[tid] = g_bn1[tid];
  const float* xb = x + (size_t)bz*65536;
  const int xr0 = 4*oy0 - 3, xc0 = 4*ox0 - 3;
  for (int j = tid; j < 70*70; j += 256){
    int r = j/70, c = j - r*70;
    int gr = xr0 + r, gc = xc0 + c;
    float v = 0.f;
    if ((unsigned)gr < 256u && (unsigned)gc < 256u) v = xb[gr*256 + gc];
    s_x[r*71 + c] = v;
  }
  __syncthreads();
  const int ty = threadIdx.y, tx = threadIdx.x;
  const int t1r0 = 2*oy0 - 1, t1c0 = 2*ox0 - 1;
  float acc[4];
#pragma unroll
  for (int o = 0; o < 4; o++) acc[o] = s_b2[o];
#pragma unroll
  for (int ph = 0; ph < 4; ph++){
    // recompute 4 channels of t1 (34x34), BN1+ReLU, into smem
    for (int idx = tid; idx < 4*1156; idx += 256){
      int c4 = idx / 1156, pos = idx - c4*1156;
      int r = pos/34, cc = pos - r*34;
      int gr = t1r0 + r, gc = t1c0 + cc;
      int ch = ph*4 + c4;
      float v = 0.f;
      if ((unsigned)gr < 128u && (unsigned)gc < 128u){
        float a = s_b1[ch];
        const float* wp = s_w1 + ch*16;
        const float* xp = s_x + (2*r)*71 + 2*cc;
#pragma unroll
        for (int kr = 0; kr < 4; kr++)
#pragma unroll
          for (int kc = 0; kc < 4; kc++)
            a = fmaf(xp[kr*71 + kc], wp[kr*4 + kc], a);
        v = fmaxf(fmaf(a, s_bn[ch], s_bn[16+ch]), 0.f);
      }
      s_t1[c4*1190 + r*35 + cc] = v;
    }
    __syncthreads();
#pragma unroll
    for (int c4 = 0; c4 < 4; c4++){
      int ch = ph*4 + c4;
      const float* sp = s_t1 + c4*1190;
#pragma unroll
      for (int ky = 0; ky < 4; ky++){
#pragma unroll
        for (int kx = 0; kx < 4; kx++){
          float v = sp[(2*ty + ky)*35 + 2*tx + kx];
#pragma unroll
          for (int o = 0; o < 4; o++)
            acc[o] = fmaf(v, s_w2[((o*16 + ch)*4 + ky)*4 + kx], acc[o]);
        }
      }
    }
    __syncthreads();
  }
  float* outb = g_t2 + bz*16384;
  int off = (oy0+ty)*64 + ox0+tx;
  float st[8];
#pragma unroll
  for (int o = 0; o < 4; o++){
    outb[o*4096 + off] = acc[o];
    st[o] = acc[o];
    st[4+o] = acc[o]*acc[o];
  }
  int lane = tid & 31, warp = tid >> 5;
#pragma unroll
  for (int v = 0; v < 8; v++){
    float r = warp_sum(st[v]);
    if (lane == 0) s_red[warp*8 + v] = r;
  }
  __syncthreads();
  if (tid < 8){
    float t = 0.f;
#pragma unroll
    for (int w = 0; w < 8; w++) t += s_red[w*8 + tid];
    int blk = (blockIdx.z*4 + blockIdx.y)*4 + blockIdx.x;
    g_partC[blk*8 + tid] = t;
  }
}

// ---------------- kernel 5: BN2+ReLU + pre1x1 + VQ + loss + post1x1 ----------------
__global__ void k_vq(const float* __restrict__ wpre, const float* __restrict__ bpre,
                     const float* __restrict__ emb,
                     const float* __restrict__ wpost, const float* __restrict__ bpost){
  __shared__ float s_e[128];
  __shared__ float s_ee[64];
  __shared__ float s_red[8];
  int tid = threadIdx.x;
  if (tid < 128) s_e[tid] = emb[tid];
  __syncthreads();
  if (tid < 64) s_ee[tid] = s_e[2*tid]*s_e[2*tid] + s_e[2*tid+1]*s_e[2*tid+1];
  __syncthreads();
  int i = blockIdx.x*256 + tid;
  int b = i >> 12, p = i & 4095;
  const float* tb = g_t2 + b*16384 + p;
  float h0 = fmaxf(fmaf(tb[0],     g_bn2[0], g_bn2[4]), 0.f);
  float h1 = fmaxf(fmaf(tb[4096],  g_bn2[1], g_bn2[5]), 0.f);
  float h2 = fmaxf(fmaf(tb[8192],  g_bn2[2], g_bn2[6]), 0.f);
  float h3 = fmaxf(fmaf(tb[12288], g_bn2[3], g_bn2[7]), 0.f);
  float z0 = bpre[0] + wpre[0]*h0 + wpre[1]*h1 + wpre[2]*h2 + wpre[3]*h3;
  float z1 = bpre[1] + wpre[4]*h0 + wpre[5]*h1 + wpre[6]*h2 + wpre[7]*h3;
  float zz = z0*z0 + z1*z1;
  float best = 3.402823466e38f; int bi = 0;
  for (int k = 0; k < 64; k++){
    float d = zz - 2.f*(z0*s_e[2*k] + z1*s_e[2*k+1]) + s_ee[k];
    if (d < best){ best = d; bi = k; }
  }
  float q0 = s_e[2*bi], q1 = s_e[2*bi+1];
  float l = (q0 - z0)*(q0 - z0) + (q1 - z1)*(q1 - z1);
  float qs0 = z0 + (q0 - z0), qs1 = z1 + (q1 - z1);
  float* db = g_di + b*16384 + p;
#pragma unroll
  for (int o = 0; o < 4; o++)
    db[o*4096] = bpost[o] + wpost[2*o]*qs0 + wpost[2*o+1]*qs1;
  int lane = tid & 31, warp = tid >> 5;
  float r = warp_sum(l);
  if (lane == 0) s_red[warp] = r;
  __syncthreads();
  if (tid == 0){
    float t = 0.f;
#pragma unroll
    for (int w = 0; w < 8; w++) t += s_red[w];
    g_partE[blockIdx.x] = t;
  }
}

// ---------------- kernel 6: convT1 BN3 partials ONLY ----------------
// grid (4,4,128): z = batch*2 + ocgroup (8 output channels).
__global__ void k_convt1s(const float* __restrict__ wd1, const float* __restrict__ bd1){
  __shared__ float s_in[4*324];
  __shared__ float s_w[512];
  __shared__ float s_b[8];
  __shared__ float s_red[8*16];
  const int g  = blockIdx.z & 1;
  const int bz = blockIdx.z >> 1;
  const int ox0 = blockIdx.x*32, oy0 = blockIdx.y*32;
  const int tid = threadIdx.y*32 + threadIdx.x;
  for (int j = tid; j < 512; j += 256){
    int c = j >> 7, rem = j & 127;
    int o8 = rem >> 4, tap = rem & 15;
    s_w[j] = wd1[c*256 + (g*8 + o8)*16 + tap];
  }
  if (tid < 8) s_b[tid] = bd1[g*8 + tid];
  const int iyb = oy0/2 - 1, ixb = ox0/2 - 1;
  const float* inb = g_di + bz*16384;
  for (int j = tid; j < 1296; j += 256){
    int c = j/324; int rem = j - c*324; int r = rem/18, cc = rem - r*18;
    int iy = iyb + r, ix = ixb + cc;
    float v = 0.f;
    if ((unsigned)iy < 64u && (unsigned)ix < 64u) v = inb[c*4096 + iy*64 + ix];
    s_in[c*324 + rem] = v;
  }
  __syncthreads();
  float st[16];
#pragma unroll
  for (int v = 0; v < 16; v++) st[v] = 0.f;
#pragma unroll
  for (int k = 0; k < 4; k++){
    int y  = oy0 + threadIdx.y + k*8;
    int x2 = ox0 + threadIdx.x;
    int iy0 = (y + 1) >> 1, ix0 = (x2 + 1) >> 1;
    int ly = iy0 - iyb, lx = ix0 - ixb;
    int kyA = y + 3 - 2*iy0, kyB = y + 1 - 2*iy0;
    int kxA = x2 + 3 - 2*ix0, kxB = x2 + 1 - 2*ix0;
    float acc[8];
#pragma unroll
    for (int o = 0; o < 8; o++) acc[o] = s_b[o];
#pragma unroll
    for (int c = 0; c < 4; c++){
      const float* sp = s_in + c*324;
      float vAA = sp[(ly-1)*18 + lx-1];
      float vAB = sp[(ly-1)*18 + lx];
      float vBA = sp[ly*18 + lx-1];
      float vBB = sp[ly*18 + lx];
      const float* wc = s_w + c*128;
#pragma unroll
      for (int o = 0; o < 8; o++){
        float a = acc[o];
        a = fmaf(vAA, wc[o*16 + kyA*4 + kxA], a);
        a = fmaf(vAB, wc[o*16 + kyA*4 + kxB], a);
        a = fmaf(vBA, wc[o*16 + kyB*4 + kxA], a);
        a = fmaf(vBB, wc[o*16 + kyB*4 + kxB], a);
        acc[o] = a;
      }
    }
#pragma unroll
    for (int o = 0; o < 8; o++){
      st[o] += acc[o];
      st[8+o] = fmaf(acc[o], acc[o], st[8+o]);
    }
  }
  int lane = tid & 31, warp = tid >> 5;
#pragma unroll
  for (int v = 0; v < 16; v++){
    float r = warp_sum(st[v]);
    if (lane == 0) s_red[warp*16 + v] = r;
  }
  __syncthreads();
  if (tid < 16){
    float t = 0.f;
#pragma unroll
    for (int w = 0; w < 8; w++) t += s_red[w*16 + tid];
    int blk = (blockIdx.z*4 + blockIdx.y)*4 + blockIdx.x;
    g_partF[blk*16 + tid] = t;
  }
}

// ---------------- kernel 8: fused convT1-recompute + BN3+ReLU + convT2 + tanh + recon ----------------
// grid (8,8,64), block (32,8). 32x32 out tile <- 18x18 t3 tile x16ch <- 12x12 di tile x4ch.
__global__ void k_convt2f(const float* __restrict__ x,
                          const float* __restrict__ wd1, const float* __restrict__ bd1,
                          const float* __restrict__ wd2, const float* __restrict__ bd2,
                          float* __restrict__ out){
  __shared__ float s_di[4*144];
  __shared__ float s_wd1[1024];
  __shared__ float s_bd1[16];
  __shared__ float s_t3[16*324];
  __shared__ float s_w[256];
  __shared__ float s_bn[32];
  __shared__ float s_red[8];
  const int bz = blockIdx.z;
  const int ox0 = blockIdx.x*32, oy0 = blockIdx.y*32;   // out coords (256x256)
  const int tid = threadIdx.y*32 + threadIdx.x;
  for (int j = tid; j < 1024; j += 256) s_wd1[j] = wd1[j];
  s_w[tid] = wd2[tid];
  if (tid < 16) s_bd1[tid] = bd1[tid];
  if (tid < 32) s_bn[tid] = g_bn3[tid];
  float bd = bd2[0];
  const int dyb = oy0/4 - 1, dxb = ox0/4 - 1;
  const float* inb = g_di + bz*16384;
  for (int j = tid; j < 4*144; j += 256){
    int c = j / 144, rem = j - c*144;
    int r = rem/12, cc = rem - r*12;
    int iy = dyb + r, ix = dxb + cc;
    float v = 0.f;
    if ((unsigned)iy < 64u && (unsigned)ix < 64u) v = inb[c*4096 + iy*64 + ix];
    s_di[c*144 + rem] = v;
  }
  __syncthreads();
  // recompute t3 18x18 x 16ch with BN3+ReLU
  const int tyb = oy0/2 - 1, txb = ox0/2 - 1;
  for (int p = tid; p < 324; p += 256){
    int py = p/18, px = p - py*18;
    int yy = tyb + py, xx = txb + px;
    if ((unsigned)yy < 128u && (unsigned)xx < 128u){
      int iy0 = (yy + 1) >> 1, ix0 = (xx + 1) >> 1;
      int ly = iy0 - dyb, lx = ix0 - dxb;
      int kyA = yy + 3 - 2*iy0, kyB = yy + 1 - 2*iy0;
      int kxA = xx + 3 - 2*ix0, kxB = xx + 1 - 2*ix0;
      float acc[16];
#pragma unroll
      for (int o = 0; o < 16; o++) acc[o] = s_bd1[o];
#pragma unroll
      for (int c = 0; c < 4; c++){
        const float* sp = s_di + c*144;
        float vAA = sp[(ly-1)*12 + lx-1];
        float vAB = sp[(ly-1)*12 + lx];
        float vBA = sp[ly*12 + lx-1];
        float vBB = sp[ly*12 + lx];
        const float* wc = s_wd1 + c*256;
#pragma unroll
        for (int o = 0; o < 16; o++){
          float a = acc[o];
          a = fmaf(vAA, wc[o*16 + kyA*4 + kxA], a);
          a = fmaf(vAB, wc[o*16 + kyA*4 + kxB], a);
          a = fmaf(vBA, wc[o*16 + kyB*4 + kxA], a);
          a = fmaf(vBB, wc[o*16 + kyB*4 + kxB], a);
          acc[o] = a;
        }
      }
#pragma unroll
      for (int o = 0; o < 16; o++)
        s_t3[o*324 + p] = fmaxf(fmaf(acc[o], s_bn[o], s_bn[16+o]), 0.f);
    } else {
#pragma unroll
      for (int o = 0; o < 16; o++) s_t3[o*324 + p] = 0.f;
    }
  }
  __syncthreads();
  const float* xb = x + (size_t)bz*65536;
  float* ob = out + (size_t)bz*65536;
  float lsum = 0.f;
#pragma unroll
  for (int k = 0; k < 4; k++){
    int y  = oy0 + threadIdx.y + k*8;
    int x2 = ox0 + threadIdx.x;
    int iy0 = (y + 1) >> 1, ix0 = (x2 + 1) >> 1;
    int ly = iy0 - tyb, lx = ix0 - txb;
    int kyA = y + 3 - 2*iy0, kyB = y + 1 - 2*iy0;
    int kxA = x2 + 3 - 2*ix0, kxB = x2 + 1 - 2*ix0;
    float acc = bd;
#pragma unroll
    for (int c = 0; c < 16; c++){
      const float* sp = s_t3 + c*324;
      const float* wc = s_w + c*16;
      acc = fmaf(sp[(ly-1)*18 + lx-1], wc[kyA*4 + kxA], acc);
      acc = fmaf(sp[(ly-1)*18 + lx],   wc[kyA*4 + kxB], acc);
      acc = fmaf(sp[ly*18 + lx-1],     wc[kyB*4 + kxA], acc);
      acc = fmaf(sp[ly*18 + lx],       wc[kyB*4 + kxB], acc);
    }
    float o = tanhf(acc);
    int off = y*256 + x2;
    ob[off] = o;
    float d = xb[off] - o;
    lsum = fmaf(d, d, lsum);
  }
  int lane = tid & 31, warp = tid >> 5;
  float r = warp_sum(lsum);
  if (lane == 0) s_red[warp] = r;
  __syncthreads();
  if (tid == 0){
    float t = 0.f;
#pragma unroll
    for (int w = 0; w < 8; w++) t += s_red[w];
    int blk = (blockIdx.z*8 + blockIdx.y)*8 + blockIdx.x;
    g_partH[blk] = t;
  }
}

// ---------------- kernel 9: final loss scalar ----------------
__global__ void k_loss(float* __restrict__ out_loss){
  __shared__ double s_red[8];
  int tid = threadIdx.x;
  double e = 0.0, h = 0.0;
  for (int i = tid; i < 1024; i += 256) e += (double)g_partE[i];
  for (int i = tid; i < 4096; i += 256) h += (double)g_partH[i];
  double t = e*1.2/524288.0 + h/4194304.0;
  int lane = tid & 31, warp = tid >> 5;
#pragma unroll
  for (int o = 16; o > 0; o >>= 1) t += __shfl_down_sync(0xffffffffu, t, o);
  if (lane == 0) s_red[warp] = t;
  __syncthreads();
  if (tid == 0){
    double s = 0.0;
    for (int w = 0; w < 8; w++) s += s_red[w];
    out_loss[0] = (float)s;
  }
}

// ---------------- launch ----------------
extern "C" void kernel_launch(void* const* d_in, const int* in_sizes, int n_in,
                              void* d_out, int out_size){
  const float* x    = (const float*)d_in[0];
  const float* w1   = (const float*)d_in[1];
  const float* b1   = (const float*)d_in[2];
  const float* g1   = (const float*)d_in[3];
  const float* be1  = (const float*)d_in[4];
  const float* w2   = (const float*)d_in[5];
  const float* b2   = (const float*)d_in[6];
  const float* g2   = (const float*)d_in[7];
  const float* be2  = (const float*)d_in[8];
  const float* wpre = (const float*)d_in[9];
  const float* bpre = (const float*)d_in[10];
  const float* emb  = (const float*)d_in[11];
  const float* wpost= (const float*)d_in[12];
  const float* bpost= (const float*)d_in[13];
  const float* wd1  = (const float*)d_in[14];
  const float* bd1  = (const float*)d_in[15];
  const float* g3   = (const float*)d_in[16];
  const float* be3  = (const float*)d_in[17];
  const float* wd2  = (const float*)d_in[18];
  const float* bd2  = (const float*)d_in[19];
  float* out = (float*)d_out;

  k_conv1s <<<dim3(4,4,64), dim3(32,8)>>>(x, w1, b1);
  k_bnfinA <<<16,256>>>(g1, be1);
  k_conv2f <<<dim3(4,4,64), dim3(16,16)>>>(x, w1, b1, w2, b2);
  k_bnfin4 <<<4,256>>>(g2, be2);
  k_vq     <<<1024,256>>>(wpre, bpre, emb, wpost, bpost);
  k_convt1s<<<dim3(4,4,128), dim3(32,8)>>>(wd1, bd1);
  k_bnfinF <<<16,256>>>(g3, be3);
  k_convt2f<<<dim3(8,8,64), dim3(32,8)>>>(x, wd1, bd1, wd2, bd2, out);
  k_loss   <<<1,256>>>(out + (out_size - 1));
}

// round 6
// speedup vs baseline: 1.6222x; 1.6222x over previous
#include <cuda_runtime.h>
#include <math.h>

// ---------------- scratch (device globals; no allocation) ----------------
__device__ float g_t1[64*16*128*128];   // conv1 raw out
__device__ float g_t3[64*16*128*128];   // convT1 raw out
__device__ float g_t2[64*4*64*64];      // conv2 out
__device__ float g_di[64*4*64*64];      // post-VQ 1x1 out
__device__ float g_partA[1024*32];
__device__ float g_partF[1024*32];
__device__ float g_partC[256*8];
__device__ float g_partE[1024];
__device__ float g_partH[4096];
__device__ float g_bn1[32];  // scale[16], shift[16]
__device__ float g_bn2[8];
__device__ float g_bn3[32];

__device__ __forceinline__ float warp_sum(float v){
#pragma unroll
  for (int o = 16; o > 0; o >>= 1) v += __shfl_down_sync(0xffffffffu, v, o);
  return v;
}

// ---------------- K1: conv1 (1->16, k4 s2 p1) + store t1 + BN1 partials ----------------
// grid (4,4,64), block (32,8). warp = oc pair, lane = column, walk 32 rows.
__global__ void k_conv1(const float* __restrict__ x, const float* __restrict__ w1,
                        const float* __restrict__ b1){
  __shared__ float s_in[66*68];
  const int bz = blockIdx.z;
  const int ox0 = blockIdx.x*32, oy0 = blockIdx.y*32;
  const int w = threadIdx.y, tx = threadIdx.x;
  const int tid = w*32 + tx;
  const int oc0 = 2*w, oc1 = 2*w + 1;
  float wr0[16], wr1[16];
#pragma unroll
  for (int j = 0; j < 16; j++){ wr0[j] = w1[oc0*16 + j]; wr1[j] = w1[oc1*16 + j]; }
  const float bb0 = b1[oc0], bb1 = b1[oc1];
  const float* xb = x + (size_t)bz*65536;
  for (int j = tid; j < 66*66; j += 256){
    int r = j/66, c = j - r*66;
    int gr = oy0*2 - 1 + r, gc = ox0*2 - 1 + c;
    float v = 0.f;
    if ((unsigned)gr < 256u && (unsigned)gc < 256u) v = xb[gr*256 + gc];
    s_in[r*68 + c] = v;
  }
  __syncthreads();
  float s0 = 0.f, q0 = 0.f, s1 = 0.f, q1 = 0.f;
  float* o0 = g_t1 + (size_t)bz*262144 + (size_t)oc0*16384 + (oy0)*128 + ox0 + tx;
  float* o1 = o0 + 16384;
  float r0[4], r1[4];
  {
    float2 u0 = *(const float2*)&s_in[0*68 + 2*tx];
    float2 u1 = *(const float2*)&s_in[0*68 + 2*tx + 2];
    float2 v0 = *(const float2*)&s_in[1*68 + 2*tx];
    float2 v1 = *(const float2*)&s_in[1*68 + 2*tx + 2];
    r0[0]=u0.x; r0[1]=u0.y; r0[2]=u1.x; r0[3]=u1.y;
    r1[0]=v0.x; r1[1]=v0.y; r1[2]=v1.x; r1[3]=v1.y;
  }
#pragma unroll 4
  for (int y = 0; y < 32; y++){
    float r2[4], r3[4];
    {
      float2 u0 = *(const float2*)&s_in[(2*y+2)*68 + 2*tx];
      float2 u1 = *(const float2*)&s_in[(2*y+2)*68 + 2*tx + 2];
      float2 v0 = *(const float2*)&s_in[(2*y+3)*68 + 2*tx];
      float2 v1 = *(const float2*)&s_in[(2*y+3)*68 + 2*tx + 2];
      r2[0]=u0.x; r2[1]=u0.y; r2[2]=u1.x; r2[3]=u1.y;
      r3[0]=v0.x; r3[1]=v0.y; r3[2]=v1.x; r3[3]=v1.y;
    }
    float a0 = bb0, a1 = bb1;
#pragma unroll
    for (int j = 0; j < 4; j++){
      a0 = fmaf(r0[j], wr0[j],    a0);  a1 = fmaf(r0[j], wr1[j],    a1);
      a0 = fmaf(r1[j], wr0[4+j],  a0);  a1 = fmaf(r1[j], wr1[4+j],  a1);
      a0 = fmaf(r2[j], wr0[8+j],  a0);  a1 = fmaf(r2[j], wr1[8+j],  a1);
      a0 = fmaf(r3[j], wr0[12+j], a0);  a1 = fmaf(r3[j], wr1[12+j], a1);
    }
    o0[y*128] = a0;  o1[y*128] = a1;
    s0 += a0; q0 = fmaf(a0, a0, q0);
    s1 += a1; q1 = fmaf(a1, a1, q1);
#pragma unroll
    for (int j = 0; j < 4; j++){ r0[j] = r2[j]; r1[j] = r3[j]; }
  }
  s0 = warp_sum(s0); q0 = warp_sum(q0);
  s1 = warp_sum(s1); q1 = warp_sum(q1);
  if (tx == 0){
    int blk = (bz*4 + blockIdx.y)*4 + blockIdx.x;
    g_partA[blk*32 + oc0] = s0;
    g_partA[blk*32 + oc1] = s1;
    g_partA[blk*32 + 16 + oc0] = q0;
    g_partA[blk*32 + 16 + oc1] = q1;
  }
}

// ---------------- BN finalize for [1024][32] partials (BN1 / BN3) ----------------
__global__ void k_bnfin32(int which, const float* __restrict__ g, const float* __restrict__ be){
  const float* part = which ? g_partF : g_partA;
  float* bn = which ? g_bn3 : g_bn1;
  const int c = blockIdx.x;
  const int tid = threadIdx.x;
  double s = 0.0, q = 0.0;
  for (int i = tid; i < 1024; i += 256){
    s += (double)part[i*32 + c];
    q += (double)part[i*32 + 16 + c];
  }
#pragma unroll
  for (int o = 16; o > 0; o >>= 1){
    s += __shfl_down_sync(0xffffffffu, s, o);
    q += __shfl_down_sync(0xffffffffu, q, o);
  }
  __shared__ double ss[8], qq[8];
  int lane = tid & 31, warp = tid >> 5;
  if (lane == 0){ ss[warp] = s; qq[warp] = q; }
  __syncthreads();
  if (tid == 0){
    double S = 0.0, Q = 0.0;
#pragma unroll
    for (int w = 0; w < 8; w++){ S += ss[w]; Q += qq[w]; }
    const double invN = 1.0/1048576.0;
    double mean = S*invN;
    double var  = Q*invN - mean*mean;
    float scale = (float)((double)g[c] / sqrt(var + 1e-5));
    bn[c] = scale;
    bn[16 + c] = be[c] - (float)mean * scale;
  }
}

// ---------------- BN2 finalize: partC [256][8] ----------------
__global__ void k_bnfinC(const float* __restrict__ g, const float* __restrict__ be){
  const int c = blockIdx.x;
  const int tid = threadIdx.x;
  double s = (double)g_partC[tid*8 + c];
  double q = (double)g_partC[tid*8 + 4 + c];
#pragma unroll
  for (int o = 16; o > 0; o >>= 1){
    s += __shfl_down_sync(0xffffffffu, s, o);
    q += __shfl_down_sync(0xffffffffu, q, o);
  }
  __shared__ double ss[8], qq[8];
  int lane = tid & 31, warp = tid >> 5;
  if (lane == 0){ ss[warp] = s; qq[warp] = q; }
  __syncthreads();
  if (tid == 0){
    double S = 0.0, Q = 0.0;
#pragma unroll
    for (int w = 0; w < 8; w++){ S += ss[w]; Q += qq[w]; }
    const double invN = 1.0/262144.0;
    double mean = S*invN;
    double var  = Q*invN - mean*mean;
    float scale = (float)((double)g[c] / sqrt(var + 1e-5));
    g_bn2[c] = scale;
    g_bn2[4 + c] = be[c] - (float)mean * scale;
  }
}

// ---------------- K3: BN1+ReLU + conv2 (16->4, k4 s2 p1) + BN2 partials ----------------
// grid (2,2,64), block (32,8). 32x32 t2 tile, per-channel staged input.
__global__ void k_conv2(const float* __restrict__ w2, const float* __restrict__ b2){
  __shared__ float s_in[66*68];
  __shared__ float s_w2[1024];
  __shared__ float s_bn[32];
  __shared__ float s_red[8*8];
  const int bz = blockIdx.z;
  const int ox0 = blockIdx.x*32, oy0 = blockIdx.y*32;
  const int ty = threadIdx.y, tx = threadIdx.x;
  const int tid = ty*32 + tx;
  for (int j = tid; j < 1024; j += 256) s_w2[j] = w2[j];
  if (tid < 32) s_bn[tid] = g_bn1[tid];
  float acc[4][4];
#pragma unroll
  for (int o = 0; o < 4; o++){
    float bo = b2[o];
#pragma unroll
    for (int k = 0; k < 4; k++) acc[o][k] = bo;
  }
  const float* t1b = g_t1 + (size_t)bz*262144;
  for (int c = 0; c < 16; c++){
    __syncthreads();
    float sc = s_bn[c], sh = s_bn[16+c];
    const float* inp = t1b + c*16384;
    for (int j = tid; j < 66*66; j += 256){
      int r = j/66, cc = j - r*66;
      int gr = 2*oy0 - 1 + r, gc = 2*ox0 - 1 + cc;
      float v = 0.f;
      if ((unsigned)gr < 128u && (unsigned)gc < 128u)
        v = fmaxf(fmaf(inp[gr*128 + gc], sc, sh), 0.f);
      s_in[r*68 + cc] = v;
    }
    __syncthreads();
#pragma unroll
    for (int ky = 0; ky < 4; ky++){
      float wk[4][4];
#pragma unroll
      for (int o = 0; o < 4; o++)
#pragma unroll
        for (int kx = 0; kx < 4; kx++)
          wk[o][kx] = s_w2[((o*16 + c)*4 + ky)*4 + kx];
#pragma unroll
      for (int k = 0; k < 4; k++){
        int rb = (2*(ty + 8*k) + ky)*68 + 2*tx;
        float2 va = *(const float2*)&s_in[rb];
        float2 vb = *(const float2*)&s_in[rb + 2];
#pragma unroll
        for (int o = 0; o < 4; o++){
          acc[o][k] = fmaf(va.x, wk[o][0], acc[o][k]);
          acc[o][k] = fmaf(va.y, wk[o][1], acc[o][k]);
          acc[o][k] = fmaf(vb.x, wk[o][2], acc[o][k]);
          acc[o][k] = fmaf(vb.y, wk[o][3], acc[o][k]);
        }
      }
    }
  }
  float st[8];
#pragma unroll
  for (int v = 0; v < 8; v++) st[v] = 0.f;
  float* outb = g_t2 + bz*16384;
#pragma unroll
  for (int k = 0; k < 4; k++){
    int off = (oy0 + ty + 8*k)*64 + ox0 + tx;
#pragma unroll
    for (int o = 0; o < 4; o++){
      float a = acc[o][k];
      outb[o*4096 + off] = a;
      st[o] += a;
      st[4+o] = fmaf(a, a, st[4+o]);
    }
  }
  int lane = tid & 31, warp = tid >> 5;
#pragma unroll
  for (int v = 0; v < 8; v++){
    float r = warp_sum(st[v]);
    if (lane == 0) s_red[warp*8 + v] = r;
  }
  __syncthreads();
  if (tid < 8){
    float t = 0.f;
#pragma unroll
    for (int w = 0; w < 8; w++) t += s_red[w*8 + tid];
    int blk = (bz*2 + blockIdx.y)*2 + blockIdx.x;
    g_partC[blk*8 + tid] = t;
  }
}

// ---------------- K5: BN2+ReLU + pre1x1 + VQ + loss + post1x1 ----------------
__global__ void k_vq(const float* __restrict__ wpre, const float* __restrict__ bpre,
                     const float* __restrict__ emb,
                     const float* __restrict__ wpost, const float* __restrict__ bpost){
  __shared__ float s_e[128];
  __shared__ float s_ee[64];
  __shared__ float s_red[8];
  int tid = threadIdx.x;
  if (tid < 128) s_e[tid] = emb[tid];
  __syncthreads();
  if (tid < 64) s_ee[tid] = s_e[2*tid]*s_e[2*tid] + s_e[2*tid+1]*s_e[2*tid+1];
  __syncthreads();
  int i = blockIdx.x*256 + tid;
  int b = i >> 12, p = i & 4095;
  const float* tb = g_t2 + b*16384 + p;
  float h0 = fmaxf(fmaf(tb[0],     g_bn2[0], g_bn2[4]), 0.f);
  float h1 = fmaxf(fmaf(tb[4096],  g_bn2[1], g_bn2[5]), 0.f);
  float h2 = fmaxf(fmaf(tb[8192],  g_bn2[2], g_bn2[6]), 0.f);
  float h3 = fmaxf(fmaf(tb[12288], g_bn2[3], g_bn2[7]), 0.f);
  float z0 = bpre[0] + wpre[0]*h0 + wpre[1]*h1 + wpre[2]*h2 + wpre[3]*h3;
  float z1 = bpre[1] + wpre[4]*h0 + wpre[5]*h1 + wpre[6]*h2 + wpre[7]*h3;
  float zz = z0*z0 + z1*z1;
  float best = 3.402823466e38f; int bi = 0;
  for (int k = 0; k < 64; k++){
    float d = zz - 2.f*(z0*s_e[2*k] + z1*s_e[2*k+1]) + s_ee[k];
    if (d < best){ best = d; bi = k; }
  }
  float q0 = s_e[2*bi], q1 = s_e[2*bi+1];
  float l = (q0 - z0)*(q0 - z0) + (q1 - z1)*(q1 - z1);
  float qs0 = z0 + (q0 - z0), qs1 = z1 + (q1 - z1);
  float* db = g_di + b*16384 + p;
#pragma unroll
  for (int o = 0; o < 4; o++)
    db[o*4096] = bpost[o] + wpost[2*o]*qs0 + wpost[2*o+1]*qs1;
  int lane = tid & 31, warp = tid >> 5;
  float r = warp_sum(l);
  if (lane == 0) s_red[warp] = r;
  __syncthreads();
  if (tid == 0){
    float t = 0.f;
#pragma unroll
    for (int w = 0; w < 8; w++) t += s_red[w];
    g_partE[blockIdx.x] = t;
  }
}

// ---------------- K6: convT1 (4->16, k4 s2 p1) + store t3 + BN3 partials ----------------
// grid (4,4,64), block (32,16). warp = oc, lane = column, row-pair walk.
__global__ void k_convt1(const float* __restrict__ wd1, const float* __restrict__ bd1){
  __shared__ float s_in[4*324];
  const int bz = blockIdx.z;
  const int ox0 = blockIdx.x*32, oy0 = blockIdx.y*32;
  const int oc = threadIdx.y, tx = threadIdx.x;
  const int tid = oc*32 + tx;
  const int kxA = (tx & 1) ? 2 : 3;
  const int kxB = (tx & 1) ? 0 : 1;
  float wA[4][4], wB[4][4];
#pragma unroll
  for (int c = 0; c < 4; c++)
#pragma unroll
    for (int ky = 0; ky < 4; ky++){
      wA[c][ky] = wd1[c*256 + oc*16 + ky*4 + kxA];
      wB[c][ky] = wd1[c*256 + oc*16 + ky*4 + kxB];
    }
  const float bb = bd1[oc];
  const int iyb = oy0/2 - 1, ixb = ox0/2 - 1;
  const float* inb = g_di + bz*16384;
  for (int j = tid; j < 1296; j += 512){
    int c = j/324, rem = j - c*324, r = rem/18, cc = rem - r*18;
    int iy = iyb + r, ix = ixb + cc;
    float v = 0.f;
    if ((unsigned)iy < 64u && (unsigned)ix < 64u) v = inb[c*4096 + iy*64 + ix];
    s_in[c*324 + rem] = v;
  }
  __syncthreads();
  const int lx = ((tx + 1) >> 1) + 1;
  float s = 0.f, q = 0.f;
  float* ob = g_t3 + (size_t)bz*262144 + (size_t)oc*16384 + oy0*128 + ox0 + tx;
  for (int a = 0; a <= 16; a++){
    int ly = a + 1;
    float accO = bb, accE = bb;
#pragma unroll
    for (int c = 0; c < 4; c++){
      const float* sp = s_in + c*324;
      float vA0 = sp[(ly-1)*18 + lx-1];
      float vA1 = sp[(ly-1)*18 + lx];
      float vB0 = sp[ly*18 + lx-1];
      float vB1 = sp[ly*18 + lx];
      accO = fmaf(vA0, wA[c][2], accO);
      accO = fmaf(vA1, wB[c][2], accO);
      accO = fmaf(vB0, wA[c][0], accO);
      accO = fmaf(vB1, wB[c][0], accO);
      accE = fmaf(vA0, wA[c][3], accE);
      accE = fmaf(vA1, wB[c][3], accE);
      accE = fmaf(vB0, wA[c][1], accE);
      accE = fmaf(vB1, wB[c][1], accE);
    }
    if (a >= 1){                       // y = 2a-1 (odd)
      ob[(2*a - 1)*128] = accO;
      s += accO; q = fmaf(accO, accO, q);
    }
    if (a <= 15){                      // y = 2a (even)
      ob[(2*a)*128] = accE;
      s += accE; q = fmaf(accE, accE, q);
    }
  }
  s = warp_sum(s); q = warp_sum(q);
  if (tx == 0){
    int blk = (bz*4 + blockIdx.y)*4 + blockIdx.x;
    g_partF[blk*32 + oc] = s;
    g_partF[blk*32 + 16 + oc] = q;
  }
}

// ---------------- K8: BN3+ReLU + convT2 (16->1) + tanh + recon partials ----------------
// grid (8,8,64), block (32,8). Parity-resolved weights in registers.
__global__ void k_convt2(const float* __restrict__ x, const float* __restrict__ wd2,
                         const float* __restrict__ bd2, float* __restrict__ out){
  __shared__ float s_t3[16*324];
  __shared__ float s_w[256];
  __shared__ float s_bn[32];
  __shared__ float s_red[8];
  const int bz = blockIdx.z;
  const int ox0 = blockIdx.x*32, oy0 = blockIdx.y*32;
  const int ty = threadIdx.y, tx = threadIdx.x;
  const int tid = ty*32 + tx;
  s_w[tid] = wd2[tid];
  if (tid < 32) s_bn[tid] = g_bn3[tid];
  const float bd = bd2[0];
  __syncthreads();
  const int tyb = oy0/2 - 1, txb = ox0/2 - 1;
  const float* inb = g_t3 + (size_t)bz*262144;
  for (int j = tid; j < 16*324; j += 256){
    int c = j/324, rem = j - c*324, r = rem/18, cc = rem - r*18;
    int iy = tyb + r, ix = txb + cc;
    float v = 0.f;
    if ((unsigned)iy < 128u && (unsigned)ix < 128u)
      v = fmaxf(fmaf(inb[c*16384 + iy*128 + ix], s_bn[c], s_bn[16+c]), 0.f);
    s_t3[c*324 + rem] = v;
  }
  __syncthreads();
  const int kyA = (ty & 1) ? 2 : 3, kyB = (ty & 1) ? 0 : 1;
  const int kxA = (tx & 1) ? 2 : 3, kxB = (tx & 1) ? 0 : 1;
  float wAA[16], wAB[16], wBA[16], wBB[16];
#pragma unroll
  for (int c = 0; c < 16; c++){
    wAA[c] = s_w[c*16 + kyA*4 + kxA];
    wAB[c] = s_w[c*16 + kyA*4 + kxB];
    wBA[c] = s_w[c*16 + kyB*4 + kxA];
    wBB[c] = s_w[c*16 + kyB*4 + kxB];
  }
  const int lx = ((tx + 1) >> 1) + 1;
  const int ly0 = ((ty + 1) >> 1) + 1;
  const float* xb = x + (size_t)bz*65536;
  float* ob = out + (size_t)bz*65536;
  float lsum = 0.f;
#pragma unroll
  for (int k = 0; k < 4; k++){
    int ly = ly0 + 4*k;
    float acc = bd;
#pragma unroll
    for (int c = 0; c < 16; c++){
      const float* sp = s_t3 + c*324;
      acc = fmaf(sp[(ly-1)*18 + lx-1], wAA[c], acc);
      acc = fmaf(sp[(ly-1)*18 + lx],   wAB[c], acc);
      acc = fmaf(sp[ly*18 + lx-1],     wBA[c], acc);
      acc = fmaf(sp[ly*18 + lx],       wBB[c], acc);
    }
    float o = tanhf(acc);
    int off = (oy0 + ty + 8*k)*256 + ox0 + tx;
    ob[off] = o;
    float d = xb[off] - o;
    lsum = fmaf(d, d, lsum);
  }
  int lane = tid & 31, warp = tid >> 5;
  float r = warp_sum(lsum);
  if (lane == 0) s_red[warp] = r;
  __syncthreads();
  if (tid == 0){
    float t = 0.f;
#pragma unroll
    for (int w = 0; w < 8; w++) t += s_red[w];
    int blk = (bz*8 + blockIdx.y)*8 + blockIdx.x;
    g_partH[blk] = t;
  }
}

// ---------------- K9: final loss scalar ----------------
__global__ void k_loss(float* __restrict__ out_loss){
  __shared__ double s_red[8];
  int tid = threadIdx.x;
  double e = 0.0, h = 0.0;
  for (int i = tid; i < 1024; i += 256) e += (double)g_partE[i];
  for (int i = tid; i < 4096; i += 256) h += (double)g_partH[i];
  double t = e*1.2/524288.0 + h/4194304.0;
  int lane = tid & 31, warp = tid >> 5;
#pragma unroll
  for (int o = 16; o > 0; o >>= 1) t += __shfl_down_sync(0xffffffffu, t, o);
  if (lane == 0) s_red[warp] = t;
  __syncthreads();
  if (tid == 0){
    double s = 0.0;
    for (int w = 0; w < 8; w++) s += s_red[w];
    out_loss[0] = (float)s;
  }
}

// ---------------- launch ----------------
extern "C" void kernel_launch(void* const* d_in, const int* in_sizes, int n_in,
                              void* d_out, int out_size){
  const float* x    = (const float*)d_in[0];
  const float* w1   = (const float*)d_in[1];
  const float* b1   = (const float*)d_in[2];
  const float* g1   = (const float*)d_in[3];
  const float* be1  = (const float*)d_in[4];
  const float* w2   = (const float*)d_in[5];
  const float* b2   = (const float*)d_in[6];
  const float* g2   = (const float*)d_in[7];
  const float* be2  = (const float*)d_in[8];
  const float* wpre = (const float*)d_in[9];
  const float* bpre = (const float*)d_in[10];
  const float* emb  = (const float*)d_in[11];
  const float* wpost= (const float*)d_in[12];
  const float* bpost= (const float*)d_in[13];
  const float* wd1  = (const float*)d_in[14];
  const float* bd1  = (const float*)d_in[15];
  const float* g3   = (const float*)d_in[16];
  const float* be3  = (const float*)d_in[17];
  const float* wd2  = (const float*)d_in[18];
  const float* bd2  = (const float*)d_in[19];
  float* out = (float*)d_out;

  k_conv1  <<<dim3(4,4,64),  dim3(32,8)>>>(x, w1, b1);
  k_bnfin32<<<16,256>>>(0, g1, be1);
  k_conv2  <<<dim3(2,2,64),  dim3(32,8)>>>(w2, b2);
  k_bnfinC <<<4,256>>>(g2, be2);
  k_vq     <<<1024,256>>>(wpre, bpre, emb, wpost, bpost);
  k_convt1 <<<dim3(4,4,64),  dim3(32,16)>>>(wd1, bd1);
  k_bnfin32<<<16,256>>>(1, g3, be3);
  k_convt2 <<<dim3(8,8,64),  dim3(32,8)>>>(x, wd2, bd2, out);
  k_loss   <<<1,256>>>(out + (out_size - 1));
}